// round 1
// baseline (speedup 1.0000x reference)
#include <cuda_runtime.h>
#include <math.h>

#define BB   8
#define NPTS 8192
#define SS   2048
#define CC   256
#define KNN  8

// Scratch (no allocation allowed): transposed features + knn results
__device__ float g_featT[BB * SS * CC];        // [B][S][C]  16.8 MB
__device__ int   g_idx[BB * NPTS * KNN];       // [B][N][K]   2 MB
__device__ float g_w  [BB * NPTS * KNN];       // [B][N][K]   2 MB

// ---------------------------------------------------------------------------
// Kernel 0: transpose sparse_feat [B,C,S] -> g_featT [B,S,C]
// ---------------------------------------------------------------------------
__global__ void transpose_feat_kernel(const float* __restrict__ feat) {
    __shared__ float tile[32][33];
    int b  = blockIdx.z;
    int s0 = blockIdx.x * 32;
    int c0 = blockIdx.y * 32;
    const float* src = feat + (size_t)b * CC * SS;

    #pragma unroll
    for (int i = threadIdx.y; i < 32; i += 8) {
        tile[i][threadIdx.x] = src[(size_t)(c0 + i) * SS + s0 + threadIdx.x];
    }
    __syncthreads();
    float* dst = g_featT + (size_t)b * SS * CC;
    #pragma unroll
    for (int i = threadIdx.y; i < 32; i += 8) {
        dst[(size_t)(s0 + i) * CC + c0 + threadIdx.x] = tile[threadIdx.x][i];
    }
}

// ---------------------------------------------------------------------------
// Kernel 1: brute-force KNN (K=8) + inverse-distance weights
// One thread per query point; sparse coords staged in SMEM as float4.
// Top-8 kept sorted DESCENDING in registers (dist[0] = current max).
// ---------------------------------------------------------------------------
__global__ void knn_kernel(const float* __restrict__ xyz,
                           const float* __restrict__ sxyz) {
    __shared__ float4 sp[SS];   // 32 KB
    int b = blockIdx.y;

    const float* sb = sxyz + (size_t)b * 3 * SS;
    for (int s = threadIdx.x; s < SS; s += blockDim.x) {
        sp[s] = make_float4(sb[s], sb[SS + s], sb[2 * SS + s], 0.0f);
    }
    __syncthreads();

    int n = blockIdx.x * blockDim.x + threadIdx.x;
    const float* xb = xyz + (size_t)b * 3 * NPTS;
    float qx = xb[n];
    float qy = xb[NPTS + n];
    float qz = xb[2 * NPTS + n];

    float dist[KNN];
    int   nidx[KNN];
    #pragma unroll
    for (int k = 0; k < KNN; k++) { dist[k] = 3.4e38f; nidx[k] = 0; }

    #pragma unroll 4
    for (int s = 0; s < SS; s++) {
        float4 p = sp[s];
        float dx = qx - p.x;
        float dy = qy - p.y;
        float dz = qz - p.z;
        float d = fmaf(dx, dx, fmaf(dy, dy, dz * dz));
        if (d < dist[0]) {
            // replace current max, bubble the new value rightward to keep
            // descending order (single pass suffices: tail is sorted)
            dist[0] = d; nidx[0] = s;
            #pragma unroll
            for (int k = 0; k < KNN - 1; k++) {
                if (dist[k] < dist[k + 1]) {
                    float td = dist[k]; dist[k] = dist[k + 1]; dist[k + 1] = td;
                    int   ti = nidx[k]; nidx[k] = nidx[k + 1]; nidx[k + 1] = ti;
                }
            }
        }
    }

    // inverse-distance weights (matches reference: 1/max(||diff||,1e-10), normalized)
    float inv[KNN];
    float ws = 0.0f;
    #pragma unroll
    for (int k = 0; k < KNN; k++) {
        float dd = sqrtf(dist[k]);
        dd = fmaxf(dd, 1e-10f);
        inv[k] = 1.0f / dd;
        ws += inv[k];
    }
    float rws = 1.0f / ws;

    int base = (b * NPTS + n) * KNN;
    #pragma unroll
    for (int k = 0; k < KNN; k++) {
        g_idx[base + k] = nidx[k];
        g_w[base + k]   = inv[k] * rws;
    }
}

// ---------------------------------------------------------------------------
// Kernel 2: weighted feature interpolation.
// Block = 32 query points x 32 channel-groups (8 channels each).
// Gather from [S,C] layout: each (neighbor, 8ch) read = one full 32B sector.
// Output writes coalesced along n.
// ---------------------------------------------------------------------------
__global__ void interp_kernel(float* __restrict__ out) {
    __shared__ int   s_idx[32][9];   // pad to 9 -> conflict-free
    __shared__ float s_w[32][9];

    int b  = blockIdx.y;
    int n0 = blockIdx.x * 32;
    int tid = threadIdx.y * 32 + threadIdx.x;

    if (tid < 32 * KNN) {
        int nn = tid / KNN;
        int kk = tid % KNN;
        int base = (b * NPTS + n0 + nn) * KNN;
        s_idx[nn][kk] = g_idx[base + kk];
        s_w[nn][kk]   = g_w[base + kk];
    }
    __syncthreads();

    int nx = threadIdx.x;         // query point within tile
    int cy = threadIdx.y;         // channel group (8 channels)

    const float* fb = g_featT + (size_t)b * SS * CC + cy * 8;
    float acc[8] = {0, 0, 0, 0, 0, 0, 0, 0};

    #pragma unroll
    for (int k = 0; k < KNN; k++) {
        int   si = s_idx[nx][k];
        float wt = s_w[nx][k];
        const float4* p = (const float4*)(fb + (size_t)si * CC);
        float4 v0 = p[0];
        float4 v1 = p[1];
        acc[0] = fmaf(wt, v0.x, acc[0]);
        acc[1] = fmaf(wt, v0.y, acc[1]);
        acc[2] = fmaf(wt, v0.z, acc[2]);
        acc[3] = fmaf(wt, v0.w, acc[3]);
        acc[4] = fmaf(wt, v1.x, acc[4]);
        acc[5] = fmaf(wt, v1.y, acc[5]);
        acc[6] = fmaf(wt, v1.z, acc[6]);
        acc[7] = fmaf(wt, v1.w, acc[7]);
    }

    float* ob = out + ((size_t)b * CC + cy * 8) * NPTS + n0 + nx;
    #pragma unroll
    for (int j = 0; j < 8; j++) {
        ob[(size_t)j * NPTS] = acc[j];
    }
}

// ---------------------------------------------------------------------------
extern "C" void kernel_launch(void* const* d_in, const int* in_sizes, int n_in,
                              void* d_out, int out_size) {
    const float* xyz         = (const float*)d_in[0];  // [B,3,N]
    const float* sparse_xyz  = (const float*)d_in[1];  // [B,3,S]
    const float* sparse_feat = (const float*)d_in[2];  // [B,C,S]
    float* out = (float*)d_out;                        // [B,C,N]

    transpose_feat_kernel<<<dim3(SS / 32, CC / 32, BB), dim3(32, 8)>>>(sparse_feat);
    knn_kernel<<<dim3(NPTS / 128, BB), 128>>>(xyz, sparse_xyz);
    interp_kernel<<<dim3(NPTS / 32, BB), dim3(32, 32)>>>(out);
}

// round 3
// speedup vs baseline: 1.3776x; 1.3776x over previous
#include <cuda_runtime.h>
#include <math.h>

#define BB   8
#define NPTS 8192
#define SS   2048
#define CC   256
#define KNN  8

// Scratch (no allocation allowed)
__device__ float g_featT[BB * SS * CC];        // [B][S][C]  16.8 MB
__device__ int   g_idx[BB * NPTS * KNN];       // [B][N][K]   2 MB
__device__ float g_w  [BB * NPTS * KNN];       // [B][N][K]   2 MB

// ---------------------------------------------------------------------------
// Kernel 0: transpose sparse_feat [B,C,S] -> g_featT [B,S,C]
// ---------------------------------------------------------------------------
__global__ void transpose_feat_kernel(const float* __restrict__ feat) {
    __shared__ float tile[32][33];
    int b  = blockIdx.z;
    int s0 = blockIdx.x * 32;
    int c0 = blockIdx.y * 32;
    const float* src = feat + (size_t)b * CC * SS;

    #pragma unroll
    for (int i = threadIdx.y; i < 32; i += 8) {
        tile[i][threadIdx.x] = src[(size_t)(c0 + i) * SS + s0 + threadIdx.x];
    }
    __syncthreads();
    float* dst = g_featT + (size_t)b * SS * CC;
    #pragma unroll
    for (int i = threadIdx.y; i < 32; i += 8) {
        dst[(size_t)(s0 + i) * CC + c0 + threadIdx.x] = tile[threadIdx.x][i];
    }
}

// ---------------------------------------------------------------------------
// Kernel 1: brute-force KNN (K=8) + inverse-distance weights.
// Direct (p-q)^2 form — REQUIRED for selection accuracy (half-form's
// cancellation noise flips ~10 near-tie selections and fails rel_err).
// One thread per query; sparse coords staged in SMEM as float4.
// Top-8 kept sorted DESCENDING in registers (dist[0] = current max).
// ---------------------------------------------------------------------------
__global__ void knn_kernel(const float* __restrict__ xyz,
                           const float* __restrict__ sxyz) {
    __shared__ float4 sp[SS];   // 32 KB
    int b = blockIdx.y;

    const float* sb = sxyz + (size_t)b * 3 * SS;
    for (int s = threadIdx.x; s < SS; s += blockDim.x) {
        sp[s] = make_float4(sb[s], sb[SS + s], sb[2 * SS + s], 0.0f);
    }
    __syncthreads();

    int n = blockIdx.x * blockDim.x + threadIdx.x;
    const float* xb = xyz + (size_t)b * 3 * NPTS;
    float qx = xb[n];
    float qy = xb[NPTS + n];
    float qz = xb[2 * NPTS + n];

    float dist[KNN];
    int   nidx[KNN];
    #pragma unroll
    for (int k = 0; k < KNN; k++) { dist[k] = 3.4e38f; nidx[k] = 0; }

    #pragma unroll 8
    for (int s = 0; s < SS; s++) {
        float4 p = sp[s];
        float dx = qx - p.x;
        float dy = qy - p.y;
        float dz = qz - p.z;
        float d = fmaf(dx, dx, fmaf(dy, dy, dz * dz));
        if (d < dist[0]) {
            dist[0] = d; nidx[0] = s;
            #pragma unroll
            for (int k = 0; k < KNN - 1; k++) {
                if (dist[k] < dist[k + 1]) {
                    float td = dist[k]; dist[k] = dist[k + 1]; dist[k + 1] = td;
                    int   ti = nidx[k]; nidx[k] = nidx[k + 1]; nidx[k + 1] = ti;
                }
            }
        }
    }

    // inverse-distance weights (reference formula)
    float inv[KNN];
    float ws = 0.0f;
    #pragma unroll
    for (int k = 0; k < KNN; k++) {
        float dd = sqrtf(dist[k]);
        dd = fmaxf(dd, 1e-10f);
        inv[k] = 1.0f / dd;
        ws += inv[k];
    }
    float rws = 1.0f / ws;

    int base = (b * NPTS + n) * KNN;
    #pragma unroll
    for (int k = 0; k < KNN; k++) {
        g_idx[base + k] = nidx[k];
        g_w[base + k]   = inv[k] * rws;
    }
}

// ---------------------------------------------------------------------------
// Kernel 2: weighted feature interpolation, channel-coalesced gathers.
// Block = 32 queries, 1024 threads.
// Phase 1: warp lanes span channels -> each gather is 512B contiguous
//          (4 packed wavefronts instead of 32 scattered ones).
//          Results staged in SMEM tile[n][257] (pad -> conflict-free phase 2).
// Phase 2: warp per channel row, lanes along n -> coalesced STG.
// ---------------------------------------------------------------------------
__global__ void interp_kernel(float* __restrict__ out) {
    __shared__ float tile[32][CC + 1];   // 32 x 257 floats = 32.9 KB
    __shared__ int   s_idx[32][KNN];
    __shared__ float s_w[32][KNN];

    int b  = blockIdx.y;
    int n0 = blockIdx.x * 32;
    int tid = threadIdx.x;

    if (tid < 32 * KNN) {
        int nn = tid / KNN;
        int kk = tid % KNN;
        int base = (b * NPTS + n0 + nn) * KNN;
        s_idx[nn][kk] = g_idx[base + kk];
        s_w[nn][kk]   = g_w[base + kk];
    }
    __syncthreads();

    // Phase 1: tc = channel group (4 floats), 64 threads (2 warps) per query.
    int tc    = tid & 63;
    int qbase = tid >> 6;            // 0..15, each handles 2 queries
    const float* fb = g_featT + (size_t)b * SS * CC + tc * 4;

    #pragma unroll
    for (int q = qbase; q < 32; q += 16) {
        float a0 = 0.f, a1 = 0.f, a2 = 0.f, a3 = 0.f;
        #pragma unroll
        for (int k = 0; k < KNN; k++) {
            int   si = s_idx[q][k];
            float wt = s_w[q][k];
            float4 v = *(const float4*)(fb + (size_t)si * CC);
            a0 = fmaf(wt, v.x, a0);
            a1 = fmaf(wt, v.y, a1);
            a2 = fmaf(wt, v.z, a2);
            a3 = fmaf(wt, v.w, a3);
        }
        int c = tc * 4;
        tile[q][c + 0] = a0;
        tile[q][c + 1] = a1;
        tile[q][c + 2] = a2;
        tile[q][c + 3] = a3;
    }
    __syncthreads();

    // Phase 2: warp w handles channel rows w, w+32, ... ; lanes along n.
    int lane = tid & 31;
    int w    = tid >> 5;             // 0..31
    float* ob = out + (size_t)b * CC * NPTS + n0 + lane;
    #pragma unroll
    for (int j = 0; j < 8; j++) {
        int c = w + j * 32;
        ob[(size_t)c * NPTS] = tile[lane][c];
    }
}

// ---------------------------------------------------------------------------
extern "C" void kernel_launch(void* const* d_in, const int* in_sizes, int n_in,
                              void* d_out, int out_size) {
    const float* xyz         = (const float*)d_in[0];  // [B,3,N]
    const float* sparse_xyz  = (const float*)d_in[1];  // [B,3,S]
    const float* sparse_feat = (const float*)d_in[2];  // [B,C,S]
    float* out = (float*)d_out;                        // [B,C,N]

    transpose_feat_kernel<<<dim3(SS / 32, CC / 32, BB), dim3(32, 8)>>>(sparse_feat);
    knn_kernel<<<dim3(NPTS / 128, BB), 128>>>(xyz, sparse_xyz);
    interp_kernel<<<dim3(NPTS / 32, BB), 1024>>>(out);
}

// round 4
// speedup vs baseline: 1.4615x; 1.0609x over previous
#include <cuda_runtime.h>
#include <cuda_fp16.h>
#include <math.h>

#define BB   8
#define NPTS 8192
#define SS   2048
#define CC   256
#define KNN  8

// Scratch (no allocation allowed)
__device__ __half g_featH[BB * SS * CC];       // [B][S][C] fp16, 8.4 MB
__device__ int    g_idx[BB * NPTS * KNN];      // [B][N][K]  2 MB
__device__ float  g_w  [BB * NPTS * KNN];      // [B][N][K]  2 MB

// ---------------------------------------------------------------------------
// Kernel 0: transpose + fp16-convert sparse_feat [B,C,S] -> g_featH [B,S,C]
// ---------------------------------------------------------------------------
__global__ void transpose_feat_kernel(const float* __restrict__ feat) {
    __shared__ float tile[32][33];
    int b  = blockIdx.z;
    int s0 = blockIdx.x * 32;
    int c0 = blockIdx.y * 32;
    const float* src = feat + (size_t)b * CC * SS;

    #pragma unroll
    for (int i = threadIdx.y; i < 32; i += 8) {
        tile[i][threadIdx.x] = src[(size_t)(c0 + i) * SS + s0 + threadIdx.x];
    }
    __syncthreads();
    __half* dst = g_featH + (size_t)b * SS * CC;
    #pragma unroll
    for (int i = threadIdx.y; i < 32; i += 8) {
        dst[(size_t)(s0 + i) * CC + c0 + threadIdx.x] =
            __float2half(tile[threadIdx.x][i]);
    }
}

// ---------------------------------------------------------------------------
// Kernel 1: brute-force KNN (K=8) + inverse-distance weights.
// Direct (p-q)^2 selection metric (REQUIRED: half-form cancellation noise
// flips near-tie selections and fails rel_err — proven in R2).
// Insert uses a PARALLEL shift: 7 independent compares + per-slot selects,
// breaking the old 7-stage dependent predicate chain (~90cyc -> ~12cyc).
// ---------------------------------------------------------------------------
__global__ void knn_kernel(const float* __restrict__ xyz,
                           const float* __restrict__ sxyz) {
    __shared__ float4 sp[SS];   // 32 KB
    int b = blockIdx.y;

    const float* sb = sxyz + (size_t)b * 3 * SS;
    for (int s = threadIdx.x; s < SS; s += blockDim.x) {
        sp[s] = make_float4(sb[s], sb[SS + s], sb[2 * SS + s], 0.0f);
    }
    __syncthreads();

    int n = blockIdx.x * blockDim.x + threadIdx.x;
    const float* xb = xyz + (size_t)b * 3 * NPTS;
    float qx = xb[n];
    float qy = xb[NPTS + n];
    float qz = xb[2 * NPTS + n];

    float dist[KNN];     // descending: dist[0] = current max
    int   nidx[KNN];
    #pragma unroll
    for (int k = 0; k < KNN; k++) { dist[k] = 3.4e38f; nidx[k] = 0; }

    #pragma unroll 8
    for (int s = 0; s < SS; s++) {
        float4 p = sp[s];
        float dx = qx - p.x;
        float dy = qy - p.y;
        float dz = qz - p.z;
        float d = fmaf(dx, dx, fmaf(dy, dy, dz * dz));
        if (d < dist[0]) {
            // c_k = (d < dist[k]); monotone prefix over the sorted list.
            // new[k] = c_{k+1} ? old[k+1] : (c_k ? d : old[k]), c_0=1, c_8=0.
            bool c1 = d < dist[1];
            bool c2 = d < dist[2];
            bool c3 = d < dist[3];
            bool c4 = d < dist[4];
            bool c5 = d < dist[5];
            bool c6 = d < dist[6];
            bool c7 = d < dist[7];
            float n0 = c1 ? dist[1] : d;
            int   m0 = c1 ? nidx[1] : s;
            float n1 = c2 ? dist[2] : (c1 ? d : dist[1]);
            int   m1 = c2 ? nidx[2] : (c1 ? s : nidx[1]);
            float n2 = c3 ? dist[3] : (c2 ? d : dist[2]);
            int   m2 = c3 ? nidx[3] : (c2 ? s : nidx[2]);
            float n3 = c4 ? dist[4] : (c3 ? d : dist[3]);
            int   m3 = c4 ? nidx[4] : (c3 ? s : nidx[3]);
            float n4 = c5 ? dist[5] : (c4 ? d : dist[4]);
            int   m4 = c5 ? nidx[5] : (c4 ? s : nidx[4]);
            float n5 = c6 ? dist[6] : (c5 ? d : dist[5]);
            int   m5 = c6 ? nidx[6] : (c5 ? s : nidx[5]);
            float n6 = c7 ? dist[7] : (c6 ? d : dist[6]);
            int   m6 = c7 ? nidx[7] : (c6 ? s : nidx[6]);
            float n7 = c7 ? d : dist[7];
            int   m7 = c7 ? s : nidx[7];
            dist[0] = n0; nidx[0] = m0;
            dist[1] = n1; nidx[1] = m1;
            dist[2] = n2; nidx[2] = m2;
            dist[3] = n3; nidx[3] = m3;
            dist[4] = n4; nidx[4] = m4;
            dist[5] = n5; nidx[5] = m5;
            dist[6] = n6; nidx[6] = m6;
            dist[7] = n7; nidx[7] = m7;
        }
    }

    // inverse-distance weights (reference formula)
    float inv[KNN];
    float ws = 0.0f;
    #pragma unroll
    for (int k = 0; k < KNN; k++) {
        float dd = sqrtf(dist[k]);
        dd = fmaxf(dd, 1e-10f);
        inv[k] = 1.0f / dd;
        ws += inv[k];
    }
    float rws = 1.0f / ws;

    int base = (b * NPTS + n) * KNN;
    #pragma unroll
    for (int k = 0; k < KNN; k++) {
        g_idx[base + k] = nidx[k];
        g_w[base + k]   = inv[k] * rws;
    }
}

// ---------------------------------------------------------------------------
// Kernel 2: weighted feature interpolation, fp16 gathers, fp32 accumulate.
// Block = 32 queries, 1024 threads.
// Phase 1: lanes span channels -> each (q,k) gather is 512B contiguous
//          (64 lanes x 8B). Stage into SMEM tile[n][257] (conflict-free).
// Phase 2: warp per channel row, lanes along n -> coalesced fp32 STG.
// ---------------------------------------------------------------------------
__global__ void interp_kernel(float* __restrict__ out) {
    __shared__ float tile[32][CC + 1];   // 32 x 257 floats = 32.9 KB
    __shared__ int   s_idx[32][KNN];
    __shared__ float s_w[32][KNN];

    int b  = blockIdx.y;
    int n0 = blockIdx.x * 32;
    int tid = threadIdx.x;

    if (tid < 32 * KNN) {
        int nn = tid / KNN;
        int kk = tid % KNN;
        int base = (b * NPTS + n0 + nn) * KNN;
        s_idx[nn][kk] = g_idx[base + kk];
        s_w[nn][kk]   = g_w[base + kk];
    }
    __syncthreads();

    // Phase 1: tc = channel group (4 halves = 8B), 64 threads per query.
    int tc    = tid & 63;
    int qbase = tid >> 6;            // 0..15, each handles 2 queries
    const __half* fb = g_featH + (size_t)b * SS * CC + tc * 4;

    #pragma unroll
    for (int q = qbase; q < 32; q += 16) {
        float a0 = 0.f, a1 = 0.f, a2 = 0.f, a3 = 0.f;
        #pragma unroll
        for (int k = 0; k < KNN; k++) {
            int   si = s_idx[q][k];
            float wt = s_w[q][k];
            uint2 raw = *(const uint2*)(fb + (size_t)si * CC);
            __half2 h0 = *reinterpret_cast<__half2*>(&raw.x);
            __half2 h1 = *reinterpret_cast<__half2*>(&raw.y);
            float2 f0 = __half22float2(h0);
            float2 f1 = __half22float2(h1);
            a0 = fmaf(wt, f0.x, a0);
            a1 = fmaf(wt, f0.y, a1);
            a2 = fmaf(wt, f1.x, a2);
            a3 = fmaf(wt, f1.y, a3);
        }
        int c = tc * 4;
        tile[q][c + 0] = a0;
        tile[q][c + 1] = a1;
        tile[q][c + 2] = a2;
        tile[q][c + 3] = a3;
    }
    __syncthreads();

    // Phase 2: warp w handles channel rows w, w+32, ... ; lanes along n.
    int lane = tid & 31;
    int w    = tid >> 5;             // 0..31
    float* ob = out + (size_t)b * CC * NPTS + n0 + lane;
    #pragma unroll
    for (int j = 0; j < 8; j++) {
        int c = w + j * 32;
        ob[(size_t)c * NPTS] = tile[lane][c];
    }
}

// ---------------------------------------------------------------------------
extern "C" void kernel_launch(void* const* d_in, const int* in_sizes, int n_in,
                              void* d_out, int out_size) {
    const float* xyz         = (const float*)d_in[0];  // [B,3,N]
    const float* sparse_xyz  = (const float*)d_in[1];  // [B,3,S]
    const float* sparse_feat = (const float*)d_in[2];  // [B,C,S]
    float* out = (float*)d_out;                        // [B,C,N]

    transpose_feat_kernel<<<dim3(SS / 32, CC / 32, BB), dim3(32, 8)>>>(sparse_feat);
    knn_kernel<<<dim3(NPTS / 128, BB), 128>>>(xyz, sparse_xyz);
    interp_kernel<<<dim3(NPTS / 32, BB), 1024>>>(out);
}